// round 8
// baseline (speedup 1.0000x reference)
#include <cuda_runtime.h>
#include <cuda_bf16.h>
#include <math.h>
#include <stdint.h>
#include <stddef.h>

// ---------------------------------------------------------------------------
// MultiHeadPooledAttention — bf16 mma.sync (HMMA) GEMMs with hi/lo split for
// fp32-like precision; pooling folded into projections. No tcgen05 / clusters
// / mbarriers: plain PTX valid on both compute_103 and sm_103a passes.
// ---------------------------------------------------------------------------

namespace {
constexpr int B_  = 2;
constexpr int L_  = 6273;   // 1 + 8*28*28
constexpr int NH_ = 8;
constexpr int LP_ = 1569;   // 1 + 8*14*14
constexpr int NB_ = 1568;
constexpr int LGLD_ = 1600; // padded logits row stride
constexpr float SCALE_ = 0.04419417382415922f;  // 512^-0.5

constexpr size_t SZ_WPT  = (size_t)3 * 4 * 512 * 512;
constexpr size_t SZ_WEFF = (size_t)3 * 4096 * 2048;
constexpr size_t SZ_WXE  = (size_t)512 * 2048;
constexpr size_t SZ_BP   = (size_t)3 * 4096;
constexpr size_t SZ_XG   = (size_t)B_ * NB_ * 2048;
constexpr size_t SZ_P    = (size_t)B_ * NH_ * LP_ * 512;
constexpr size_t SZ_PX   = (size_t)B_ * LP_ * 512;
constexpr size_t SZ_EMB  = (size_t)NB_ * 512;
constexpr size_t SZ_LG   = (size_t)B_ * NH_ * LP_ * LGLD_;
constexpr size_t SZ_ST   = (size_t)B_ * LP_ * 4096;

constexpr size_t OFF_WPT  = 0;
constexpr size_t OFF_WEFF = OFF_WPT + SZ_WPT;
constexpr size_t OFF_WXE  = OFF_WEFF + SZ_WEFF;
constexpr size_t OFF_BP   = OFF_WXE + SZ_WXE;
constexpr size_t OFF_XG   = OFF_BP + SZ_BP;
constexpr size_t OFF_PQ   = OFF_XG + SZ_XG;
constexpr size_t OFF_PK   = OFF_PQ + SZ_P;
constexpr size_t OFF_PV   = OFF_PK + SZ_P;
constexpr size_t OFF_K2   = OFF_PV + SZ_P;
constexpr size_t OFF_PX   = OFF_K2 + SZ_P;
constexpr size_t OFF_EMB  = OFF_PX + SZ_PX;
constexpr size_t OFF_LG   = OFF_EMB + SZ_EMB;
constexpr size_t OFF_ST   = OFF_LG + SZ_LG;
constexpr size_t SZ_TOTAL = OFF_ST + SZ_ST;
}  // namespace

__device__ float g_scratch[SZ_TOTAL];

// ------------------------------- PTX helpers -------------------------------

__device__ __forceinline__ uint32_t smem_u32(const void* p) {
  uint32_t a;
  asm("{ .reg .u64 t; cvta.to.shared.u64 t, %1; cvt.u32.u64 %0, t; }"
      : "=r"(a) : "l"(p));
  return a;
}

__device__ __forceinline__ void ldm4(uint32_t* d, uint32_t addr) {
  asm volatile("ldmatrix.sync.aligned.m8n8.x4.shared.b16 {%0,%1,%2,%3}, [%4];"
               : "=r"(d[0]), "=r"(d[1]), "=r"(d[2]), "=r"(d[3]) : "r"(addr));
}

__device__ __forceinline__ void mma16816(float* c, const uint32_t* a,
                                         const uint32_t* b) {
  asm volatile(
      "mma.sync.aligned.m16n8k16.row.col.f32.bf16.bf16.f32 "
      "{%0,%1,%2,%3}, {%4,%5,%6,%7}, {%8,%9}, {%0,%1,%2,%3};"
      : "+f"(c[0]), "+f"(c[1]), "+f"(c[2]), "+f"(c[3])
      : "r"(a[0]), "r"(a[1]), "r"(a[2]), "r"(a[3]), "r"(b[0]), "r"(b[1]));
}

__device__ __forceinline__ void sts_v2(uint32_t addr, uint32_t a, uint32_t b) {
  asm volatile("st.shared.v2.b32 [%0], {%1,%2};" :: "r"(addr), "r"(a), "r"(b));
}
__device__ __forceinline__ void sts32(uint32_t addr, uint32_t a) {
  asm volatile("st.shared.b32 [%0], %1;" :: "r"(addr), "r"(a));
}

// bf16 hi/lo split: hi = bf16(x); lo = bf16(x - hi).
__device__ __forceinline__ uint16_t bfc(float x, int lo) {
  __nv_bfloat16 h = __float2bfloat16(x);
  if (lo) h = __float2bfloat16(x - __bfloat162float(h));
  return __bfloat16_as_ushort(h);
}
__device__ __forceinline__ uint32_t pack2(float x, float y, int lo) {
  return (uint32_t)bfc(x, lo) | ((uint32_t)bfc(y, lo) << 16);
}

// ------------------------------ tile loaders --------------------------------
// SMEM tile: 128 rows x 32 bf16, row stride 80 bytes (conflict-free ldmatrix).

constexpr int ROWB = 80;
constexpr int TILEB = 128 * ROWB;  // 10240

// Rows-major operand (rows = M or N, cols = K). Produces hi (and lo) tiles.
__device__ __forceinline__ void load_km(const float* S, int ld, int rmax,
                                        int Kmax, int r0, int k0, uint32_t hiB,
                                        uint32_t loB, bool doLo, int tid) {
#pragma unroll
  for (int i = 0; i < 4; i++) {
    int idx = tid + 256 * i;        // 1024 float4 slots
    int row = idx >> 3;             // 8 float4 per row
    int kq = idx & 7;
    int gr = r0 + row, gk = k0 + kq * 4;
    float4 v = make_float4(0.f, 0.f, 0.f, 0.f);
    if (gr < rmax) {
      const float* sp = S + (size_t)gr * ld;
      if (gk + 3 < Kmax) {
        v = *reinterpret_cast<const float4*>(sp + gk);
      } else {
        if (gk < Kmax)     v.x = sp[gk];
        if (gk + 1 < Kmax) v.y = sp[gk + 1];
        if (gk + 2 < Kmax) v.z = sp[gk + 2];
        if (gk + 3 < Kmax) v.w = sp[gk + 3];
      }
    }
    uint32_t off = (uint32_t)(row * ROWB + kq * 8);
    sts_v2(hiB + off, pack2(v.x, v.y, 0), pack2(v.z, v.w, 0));
    if (doLo) sts_v2(loB + off, pack2(v.x, v.y, 1), pack2(v.z, v.w, 1));
  }
}

// B stored (K,N) row-major: transpose on load into N-major rows.
__device__ __forceinline__ void load_tr(const float* S, int ld, int nmax,
                                        int Kmax, int n0, int k0, uint32_t hiB,
                                        uint32_t loB, bool doLo, int tid) {
#pragma unroll
  for (int i = 0; i < 2; i++) {
    int u = tid + 256 * i;          // 512 pair-units
    int n4 = u & 31;                // group of 4 N values
    int k = (u >> 5) * 2;           // even k
    int gk = k0 + k, gn = n0 + n4 * 4;
    float a0[4] = {0.f, 0.f, 0.f, 0.f};
    float a1[4] = {0.f, 0.f, 0.f, 0.f};
    if (gn + 3 < nmax) {
      if (gk < Kmax) {
        float4 t = *reinterpret_cast<const float4*>(S + (size_t)gk * ld + gn);
        a0[0] = t.x; a0[1] = t.y; a0[2] = t.z; a0[3] = t.w;
      }
      if (gk + 1 < Kmax) {
        float4 t = *reinterpret_cast<const float4*>(S + (size_t)(gk + 1) * ld + gn);
        a1[0] = t.x; a1[1] = t.y; a1[2] = t.z; a1[3] = t.w;
      }
    } else {
#pragma unroll
      for (int jj = 0; jj < 4; jj++) {
        if (gn + jj < nmax) {
          if (gk < Kmax)     a0[jj] = S[(size_t)gk * ld + gn + jj];
          if (gk + 1 < Kmax) a1[jj] = S[(size_t)(gk + 1) * ld + gn + jj];
        }
      }
    }
#pragma unroll
    for (int jj = 0; jj < 4; jj++) {
      uint32_t off = (uint32_t)((n4 * 4 + jj) * ROWB + k * 2);
      sts32(hiB + off, pack2(a0[jj], a1[jj], 0));
      if (doLo) sts32(loB + off, pack2(a0[jj], a1[jj], 1));
    }
  }
}

// ----------------------------- HMMA GEMM kernel -----------------------------
// C[M,N] = A[M,K] * op(B); tile 128(M) x 128(N) x 32(K-chunk); 256 threads.
// SPLIT: per chunk run 3 sub-passes hiA*hiB + loA*hiB + hiA*loB.

template <typename P, bool SPLIT>
__global__ __launch_bounds__(256) void gemm_mm(P p) {
  __shared__ __align__(16) char sm[4 * TILEB];  // Ahi, Alo, Bhi, Blo
  uint32_t base = smem_u32(sm);
  const uint32_t Ahi = base, Alo = base + TILEB;
  const uint32_t Bhi = base + 2 * TILEB, Blo = base + 3 * TILEB;

  const int tid = threadIdx.x;
  const int wid = tid >> 5, lane = tid & 31;
  const int wm = wid >> 1, wn = wid & 1;   // warp tile: 32(M) x 64(N)
  const int lj = lane >> 3, lr = lane & 7;

  const int z = blockIdx.z;
  const float* A = p.Aptr(z);
  const float* Bm = p.Bptr(z);
  const int M = p.M, N = p.N, K = p.K, lda = p.lda, ldb = p.ldb;
  const int m0 = blockIdx.y * 128, n0 = blockIdx.x * 128;

  float acc[2][8][4];
#pragma unroll
  for (int a = 0; a < 2; a++)
#pragma unroll
    for (int b = 0; b < 8; b++)
#pragma unroll
      for (int c = 0; c < 4; c++) acc[a][b][c] = 0.f;

  // ldmatrix lane address components (byte offsets within tile)
  const uint32_t aRow = (uint32_t)(wm * 32 + (lj & 1) * 8 + lr);
  const uint32_t aCol = (uint32_t)((lj >> 1) * 16);
  const uint32_t bRow = (uint32_t)(wn * 64 + (lj >> 1) * 8 + lr);
  const uint32_t bCol = (uint32_t)((lj & 1) * 16);

  const int nch = (K + 31) >> 5;
  for (int ch = 0; ch < nch; ch++) {
    int k0 = ch << 5;
    __syncthreads();
    load_km(A, lda, M, K, m0, k0, Ahi, Alo, SPLIT, tid);
    if (P::BT) load_km(Bm, ldb, N, K, n0, k0, Bhi, Blo, SPLIT, tid);
    else       load_tr(Bm, ldb, N, K, n0, k0, Bhi, Blo, SPLIT, tid);
    __syncthreads();

    const int npass = SPLIT ? 3 : 1;
    for (int ps = 0; ps < npass; ps++) {
      uint32_t aT = (ps == 1) ? Alo : Ahi;
      uint32_t bT = (ps == 2) ? Blo : Bhi;
#pragma unroll
      for (int ks = 0; ks < 2; ks++) {
        uint32_t afr[2][4];
#pragma unroll
        for (int mi = 0; mi < 2; mi++)
          ldm4(afr[mi], aT + (aRow + mi * 16) * ROWB + ks * 32 + aCol);
        uint32_t bfr[8][2];
#pragma unroll
        for (int nb = 0; nb < 4; nb++) {
          uint32_t t[4];
          ldm4(t, bT + (bRow + nb * 16) * ROWB + ks * 32 + bCol);
          bfr[2 * nb][0] = t[0];
          bfr[2 * nb][1] = t[1];
          bfr[2 * nb + 1][0] = t[2];
          bfr[2 * nb + 1][1] = t[3];
        }
#pragma unroll
        for (int mi = 0; mi < 2; mi++)
#pragma unroll
          for (int ni = 0; ni < 8; ni++)
            mma16816(acc[mi][ni], afr[mi], bfr[ni]);
      }
    }
  }

  // Epilogue: D frag: c0,c1 -> (row lane/4, col 2*(lane%4)+{0,1}); c2,c3 -> row+8.
  const int rr = lane >> 2, cc = (lane & 3) * 2;
#pragma unroll
  for (int mi = 0; mi < 2; mi++) {
#pragma unroll
    for (int ni = 0; ni < 8; ni++) {
      int rb = m0 + wm * 32 + mi * 16 + rr;
      int cb = n0 + wn * 64 + ni * 8 + cc;
      if (rb < M) {
        if (cb < N)     p.store(z, rb, cb,     acc[mi][ni][0]);
        if (cb + 1 < N) p.store(z, rb, cb + 1, acc[mi][ni][1]);
      }
      if (rb + 8 < M) {
        if (cb < N)     p.store(z, rb + 8, cb,     acc[mi][ni][2]);
        if (cb + 1 < N) p.store(z, rb + 8, cb + 1, acc[mi][ni][3]);
      }
    }
  }
}

// ----------------------------- GEMM problem defs ----------------------------

struct WeffP {
  static constexpr bool BT = false;
  int M, N, K, lda, ldb;
  const float* wpT;
  const float* Wq; const float* Wk; const float* Wv;
  float* Weff;
  __device__ const float* Aptr(int z) const {
    int ti = z >> 5, t = z & 3;
    return wpT + ((size_t)(ti * 4 + t) << 18);
  }
  __device__ const float* Bptr(int z) const {
    int ti = z >> 5, n = (z & 31) >> 2;
    const float* W = (ti == 0) ? Wq : ((ti == 1) ? Wk : Wv);
    return W + (size_t)n * 512 * 512;
  }
  __device__ void store(int z, int r, int c, float v) const {
    int ti = z >> 5, n = (z & 31) >> 2, t = z & 3;
    Weff[(size_t)ti * 4096 * 2048 + (size_t)(n * 512 + r) * 2048 + t * 512 + c] = v;
  }
};

struct PoolP {
  static constexpr bool BT = true;
  int M, N, K, lda, ldb;
  const float* Xg;
  const float* Weff;
  const float* bias;  // may be null
  float* out;
  int nh;
  __device__ const float* Aptr(int) const { return Xg; }
  __device__ const float* Bptr(int) const { return Weff; }
  __device__ void store(int, int r, int c, float v) const {
    int b = r / NB_, o = r % NB_;
    if (bias) v += bias[c];
    out[((size_t)(b * nh + (c >> 9)) * LP_ + 1 + o) * 512 + (c & 511)] = v;
  }
};

struct LogitsP {
  static constexpr bool BT = true;
  int M, N, K, lda, ldb;
  const float* PQ;
  const float* K2;
  float* lg;
  __device__ const float* Aptr(int z) const { return PQ + (size_t)z * LP_ * 512; }
  __device__ const float* Bptr(int z) const { return K2 + (size_t)z * LP_ * 512; }
  __device__ void store(int z, int r, int c, float v) const {
    lg[(size_t)z * LP_ * LGLD_ + (size_t)r * LGLD_ + c] = v;
  }
};

struct AVP {
  static constexpr bool BT = false;
  int M, N, K, lda, ldb;
  const float* attn;
  const float* PV;
  const float* PQ;
  float* stacked;
  __device__ const float* Aptr(int z) const { return attn + (size_t)z * LP_ * LGLD_; }
  __device__ const float* Bptr(int z) const { return PV + (size_t)z * LP_ * 512; }
  __device__ void store(int z, int r, int c, float v) const {
    float pq = PQ[(size_t)z * LP_ * 512 + (size_t)r * 512 + c];
    v += (r > 0 ? 2.f : 1.f) * pq;
    int b = z >> 3, n = z & 7;
    stacked[((size_t)b * LP_ + r) * 4096 + n * 512 + c] = v;
  }
};

struct FinalP {
  static constexpr bool BT = true;
  int M, N, K, lda, ldb;
  const float* stacked;
  const float* Wd;
  const float* bd;
  const float* PX;
  float* y;
  __device__ const float* Aptr(int) const { return stacked; }
  __device__ const float* Bptr(int) const { return Wd; }
  __device__ void store(int, int r, int c, float v) const {
    y[(size_t)r * 512 + c] = v + bd[c] + PX[(size_t)r * 512 + c];
  }
};

// ------------------------------ helper kernels ------------------------------

__global__ void k_transpose_wp(const float* wpq, const float* wpk,
                               const float* wpv, float* wpT) {
  size_t idx = (size_t)blockIdx.x * blockDim.x + threadIdx.x;
  if (idx >= SZ_WPT) return;
  int ti = (int)(idx / (512 * 512 * 4));
  int r = (int)(idx % (512 * 512 * 4));
  int c = r / 2048;
  int d = (r % 2048) >> 2;
  int t = r & 3;
  const float* wp = (ti == 0) ? wpq : ((ti == 1) ? wpk : wpv);
  wpT[((size_t)(ti * 4 + t) * 512 + c) * 512 + d] = wp[r];
}

__global__ void k_wxe(const float* wpx, float* WXe) {
  size_t idx = (size_t)blockIdx.x * blockDim.x + threadIdx.x;
  if (idx >= SZ_WXE) return;
  int c = (int)(idx / 2048);
  int t = (int)((idx % 2048) / 512);
  int m = (int)(idx & 511);
  WXe[idx] = wpx[(size_t)c * 2048 + m * 4 + t];
}

__global__ void k_bpool(const float* wpq, const float* wpk, const float* wpv,
                        const float* bq, const float* bk, const float* bv,
                        float* bpool) {
  int j = blockIdx.x * blockDim.x + threadIdx.x;
  if (j >= 3 * 4096) return;
  int ti = j / 4096, h = j % 4096, n = h >> 9, c = h & 511;
  const float* wp = (ti == 0) ? wpq : ((ti == 1) ? wpk : wpv);
  const float* b = (ti == 0) ? bq : ((ti == 1) ? bk : bv);
  float s = 0.f;
  for (int d = 0; d < 512; d++) {
    float bb = b[n * 512 + d];
    const float* w = wp + (size_t)c * 2048 + d * 4;
    s += (w[0] + w[1] + w[2] + w[3]) * bb;
  }
  bpool[j] = s;
}

__global__ void k_gather(const float* x, float* Xg) {
  size_t idx = (size_t)blockIdx.x * blockDim.x + threadIdx.x;
  if (idx >= SZ_XG) return;
  int r = (int)(idx / 2048);
  int col = (int)(idx & 2047);
  int t = col >> 9, m = col & 511;
  int b = r / NB_, o = r % NB_;
  int t2 = o / 196, hh = (o / 14) % 14, ww = o % 14;
  int kh = t >> 1, kw = t & 1;
  int row = 1 + (t2 * 28 + 2 * hh + kh) * 28 + 2 * ww + kw;
  Xg[idx] = x[((size_t)b * L_ + row) * 512 + m];
}

__global__ void k_cls(const float* x, const float* Wq, const float* bq,
                      const float* Wk, const float* bk, const float* Wv,
                      const float* bv, float* PQ, float* PK, float* PV,
                      float* PX) {
  int idx = blockIdx.x * blockDim.x + threadIdx.x;
  if (idx < 2 * 12288) {
    int b = idx / 12288, j = idx % 12288, ti = j / 4096, jj = j & 4095;
    const float* W = (ti == 0) ? Wq : ((ti == 1) ? Wk : Wv);
    const float* bias = (ti == 0) ? bq : ((ti == 1) ? bk : bv);
    const float* xr = x + (size_t)b * L_ * 512;
    const float* wr = W + (size_t)jj * 512;
    float s = bias[jj];
    for (int m = 0; m < 512; m++) s += xr[m] * wr[m];
    int n = jj >> 9, c = jj & 511;
    float* out = (ti == 0) ? PQ : ((ti == 1) ? PK : PV);
    out[(size_t)(b * 8 + n) * LP_ * 512 + c] = s;
  } else if (idx < 2 * 12288 + 2 * 512) {
    int k = idx - 2 * 12288;
    int b = k >> 9, c = k & 511;
    PX[(size_t)b * LP_ * 512 + c] = x[(size_t)b * L_ * 512 + c];
  }
}

__device__ __forceinline__ float sincos_val(int pos, int c, int dim) {
  int half = dim / 2;
  bool is_cos = c >= half;
  int i = is_cos ? c - half : c;
  float omega = powf(10000.f, -((float)i) / (float)half);
  float ang = (float)pos * omega;
  return is_cos ? cosf(ang) : sinf(ang);
}

__global__ void k_emb(float* emb) {
  size_t idx = (size_t)blockIdx.x * blockDim.x + threadIdx.x;
  if (idx >= SZ_EMB) return;
  int k = (int)(idx >> 9);
  int c = (int)(idx & 511);
  int t2 = k / 196, h2 = (k / 14) % 14, w2 = k % 14;
  float v;
  if (c < 170) v = sincos_val(t2, c, 170);
  else if (c < 340) v = sincos_val(h2, c - 170, 170);
  else v = sincos_val(w2, c - 340, 172);
  emb[idx] = v;
}

__global__ void k_k2(const float* PK, const float* emb, float* K2) {
  size_t idx = (size_t)blockIdx.x * blockDim.x + threadIdx.x;
  if (idx >= SZ_P) return;
  size_t rem = idx % ((size_t)LP_ * 512);
  int k = (int)(rem >> 9);
  int c = (int)(rem & 511);
  float v = SCALE_ * PK[idx];
  if (k > 0) v += emb[(size_t)(k - 1) * 512 + c];
  K2[idx] = v;
}

__global__ void k_row0(const float* PQ, const float* PK, float* lg) {
  int z = blockIdx.y;
  int kq = blockIdx.x * 8 + (threadIdx.x >> 5);
  int lane = threadIdx.x & 31;
  if (kq >= LP_) return;
  const float* q = PQ + (size_t)z * LP_ * 512;
  const float* kr = PK + (size_t)z * LP_ * 512 + (size_t)kq * 512;
  float s = 0.f;
  for (int i = lane; i < 512; i += 32) s += q[i] * kr[i];
#pragma unroll
  for (int o = 16; o; o >>= 1) s += __shfl_xor_sync(0xFFFFFFFFu, s, o);
  if (lane == 0) lg[(size_t)z * LP_ * LGLD_ + kq] = s * SCALE_;
}

__global__ void k_softmax(float* lg) {
  int z = blockIdx.y, q = blockIdx.x;
  float* row = lg + ((size_t)z * LP_ + q) * LGLD_;
  int tid = threadIdx.x;
  __shared__ float red[256];
  float mx = -1e30f;
  for (int i = tid; i < LP_; i += 256) mx = fmaxf(mx, row[i]);
  red[tid] = mx;
  __syncthreads();
  for (int s = 128; s > 0; s >>= 1) {
    if (tid < s) red[tid] = fmaxf(red[tid], red[tid + s]);
    __syncthreads();
  }
  mx = red[0];
  __syncthreads();
  float sum = 0.f;
  for (int i = tid; i < LP_; i += 256) {
    float e = expf(row[i] - mx);
    row[i] = e;
    sum += e;
  }
  red[tid] = sum;
  __syncthreads();
  for (int s = 128; s > 0; s >>= 1) {
    if (tid < s) red[tid] += red[tid + s];
    __syncthreads();
  }
  float inv = 1.f / red[0];
  for (int i = tid; i < LP_; i += 256) row[i] *= inv;
}

__global__ void k_ln(float* y, const float* gamma, const float* beta) {
  int row = blockIdx.x;
  float* yr = y + (size_t)row * 512;
  int tid = threadIdx.x;
  float v0 = yr[tid], v1 = yr[tid + 256];
  __shared__ float red[256];
  red[tid] = v0 + v1;
  __syncthreads();
  for (int s = 128; s > 0; s >>= 1) {
    if (tid < s) red[tid] += red[tid + s];
    __syncthreads();
  }
  float mu = red[0] * (1.f / 512.f);
  __syncthreads();
  float d0 = v0 - mu, d1 = v1 - mu;
  red[tid] = d0 * d0 + d1 * d1;
  __syncthreads();
  for (int s = 128; s > 0; s >>= 1) {
    if (tid < s) red[tid] += red[tid + s];
    __syncthreads();
  }
  float inv = rsqrtf(red[0] * (1.f / 512.f) + 1e-5f);
  yr[tid] = d0 * inv * gamma[tid] + beta[tid];
  yr[tid + 256] = d1 * inv * gamma[tid + 256] + beta[tid + 256];
}

// --------------------------------- launcher ---------------------------------

extern "C" void kernel_launch(void* const* d_in, const int* in_sizes, int n_in,
                              void* d_out, int out_size) {
  (void)in_sizes; (void)n_in; (void)out_size;
  const float* x   = (const float*)d_in[0];
  const float* Wq  = (const float*)d_in[1];
  const float* bq  = (const float*)d_in[2];
  const float* Wk  = (const float*)d_in[3];
  const float* bk  = (const float*)d_in[4];
  const float* Wv  = (const float*)d_in[5];
  const float* bv  = (const float*)d_in[6];
  const float* wpq = (const float*)d_in[7];
  const float* wpk = (const float*)d_in[8];
  const float* wpv = (const float*)d_in[9];
  const float* wpx = (const float*)d_in[10];
  const float* Wd  = (const float*)d_in[11];
  const float* bd  = (const float*)d_in[12];
  const float* gamma = (const float*)d_in[13];
  const float* beta  = (const float*)d_in[14];
  float* y = (float*)d_out;

  float* S = nullptr;
  cudaGetSymbolAddress((void**)&S, g_scratch);

  float* wpT   = S + OFF_WPT;
  float* Weff  = S + OFF_WEFF;
  float* WXe   = S + OFF_WXE;
  float* bpool = S + OFF_BP;
  float* Xg    = S + OFF_XG;
  float* PQ    = S + OFF_PQ;
  float* PK    = S + OFF_PK;
  float* PV    = S + OFF_PV;
  float* K2    = S + OFF_K2;
  float* PX    = S + OFF_PX;
  float* emb   = S + OFF_EMB;
  float* lg    = S + OFF_LG;
  float* st    = S + OFF_ST;

  k_transpose_wp<<<(int)((SZ_WPT + 255) / 256), 256>>>(wpq, wpk, wpv, wpT);
  k_wxe<<<(int)((SZ_WXE + 255) / 256), 256>>>(wpx, WXe);
  k_bpool<<<(3 * 4096 + 255) / 256, 256>>>(wpq, wpk, wpv, bq, bk, bv, bpool);

  {
    WeffP p;
    p.M = 512; p.N = 512; p.K = 512; p.lda = 512; p.ldb = 512;
    p.wpT = wpT; p.Wq = Wq; p.Wk = Wk; p.Wv = Wv; p.Weff = Weff;
    gemm_mm<WeffP, true><<<dim3(4, 4, 96), 256>>>(p);
  }

  k_gather<<<(int)((SZ_XG + 255) / 256), 256>>>(x, Xg);

  {
    PoolP p;
    p.M = B_ * NB_; p.K = 2048; p.lda = 2048; p.ldb = 2048;
    p.Xg = Xg;
    p.N = 4096; p.nh = 8;
    p.Weff = Weff;                           p.bias = bpool;        p.out = PQ;
    gemm_mm<PoolP, true><<<dim3(32, 25, 1), 256>>>(p);
    p.Weff = Weff + (size_t)4096 * 2048;     p.bias = bpool + 4096; p.out = PK;
    gemm_mm<PoolP, false><<<dim3(32, 25, 1), 256>>>(p);
    p.Weff = Weff + (size_t)2 * 4096 * 2048; p.bias = bpool + 8192; p.out = PV;
    gemm_mm<PoolP, true><<<dim3(32, 25, 1), 256>>>(p);
    p.N = 512; p.nh = 1;
    p.Weff = WXe; p.bias = nullptr; p.out = PX;
    gemm_mm<PoolP, true><<<dim3(4, 25, 1), 256>>>(p);
  }

  k_cls<<<(2 * 12288 + 2 * 512 + 255) / 256, 256>>>(x, Wq, bq, Wk, bk, Wv, bv,
                                                    PQ, PK, PV, PX);
  k_emb<<<(int)((SZ_EMB + 255) / 256), 256>>>(emb);
  k_k2<<<(int)((SZ_P + 255) / 256), 256>>>(PK, emb, K2);

  {
    LogitsP p;
    p.M = LP_; p.N = LP_; p.K = 512; p.lda = 512; p.ldb = 512;
    p.PQ = PQ; p.K2 = K2; p.lg = lg;
    gemm_mm<LogitsP, true><<<dim3(13, 13, 16), 256>>>(p);
  }

  k_row0<<<dim3((LP_ + 7) / 8, 16), 256>>>(PQ, PK, lg);
  k_softmax<<<dim3(LP_, 16), 256>>>(lg);

  {
    AVP p;
    p.M = LP_; p.N = 512; p.K = LP_; p.lda = LGLD_; p.ldb = 512;
    p.attn = lg; p.PV = PV; p.PQ = PQ; p.stacked = st;
    gemm_mm<AVP, true><<<dim3(4, 13, 16), 256>>>(p);
  }

  {
    FinalP p;
    p.M = B_ * LP_; p.N = 512; p.K = 4096; p.lda = 4096; p.ldb = 4096;
    p.stacked = st; p.Wd = Wd; p.bd = bd; p.PX = PX; p.y = y;
    gemm_mm<FinalP, true><<<dim3(4, 25, 1), 256>>>(p);
  }

  k_ln<<<B_ * LP_, 256>>>(y, gamma, beta);
}

// round 9
// speedup vs baseline: 2.2862x; 2.2862x over previous
#include <cuda_runtime.h>
#include <cuda_bf16.h>
#include <math.h>
#include <stdint.h>
#include <stddef.h>

// ---------------------------------------------------------------------------
// MultiHeadPooledAttention — bf16 mma.sync (HMMA) GEMMs with hi/lo split for
// fp32-like precision; pooling folded into projections. Register-staged
// software pipeline: LDG of chunk k+1 overlaps MMA of chunk k.
// ---------------------------------------------------------------------------

namespace {
constexpr int B_  = 2;
constexpr int L_  = 6273;   // 1 + 8*28*28
constexpr int NH_ = 8;
constexpr int LP_ = 1569;   // 1 + 8*14*14
constexpr int NB_ = 1568;
constexpr int LGLD_ = 1600; // padded logits row stride
constexpr float SCALE_ = 0.04419417382415922f;  // 512^-0.5

constexpr size_t SZ_WPT  = (size_t)3 * 4 * 512 * 512;
constexpr size_t SZ_WEFF = (size_t)3 * 4096 * 2048;
constexpr size_t SZ_WXE  = (size_t)512 * 2048;
constexpr size_t SZ_BP   = (size_t)3 * 4096;
constexpr size_t SZ_XG   = (size_t)B_ * NB_ * 2048;
constexpr size_t SZ_P    = (size_t)B_ * NH_ * LP_ * 512;
constexpr size_t SZ_PX   = (size_t)B_ * LP_ * 512;
constexpr size_t SZ_EMB  = (size_t)NB_ * 512;
constexpr size_t SZ_LG   = (size_t)B_ * NH_ * LP_ * LGLD_;
constexpr size_t SZ_ST   = (size_t)B_ * LP_ * 4096;

constexpr size_t OFF_WPT  = 0;
constexpr size_t OFF_WEFF = OFF_WPT + SZ_WPT;
constexpr size_t OFF_WXE  = OFF_WEFF + SZ_WEFF;
constexpr size_t OFF_BP   = OFF_WXE + SZ_WXE;
constexpr size_t OFF_XG   = OFF_BP + SZ_BP;
constexpr size_t OFF_PQ   = OFF_XG + SZ_XG;
constexpr size_t OFF_PK   = OFF_PQ + SZ_P;
constexpr size_t OFF_PV   = OFF_PK + SZ_P;
constexpr size_t OFF_K2   = OFF_PV + SZ_P;
constexpr size_t OFF_PX   = OFF_K2 + SZ_P;
constexpr size_t OFF_EMB  = OFF_PX + SZ_PX;
constexpr size_t OFF_LG   = OFF_EMB + SZ_EMB;
constexpr size_t OFF_ST   = OFF_LG + SZ_LG;
constexpr size_t SZ_TOTAL = OFF_ST + SZ_ST;
}  // namespace

__device__ float g_scratch[SZ_TOTAL];

// ------------------------------- PTX helpers -------------------------------

__device__ __forceinline__ uint32_t smem_u32(const void* p) {
  uint32_t a;
  asm("{ .reg .u64 t; cvta.to.shared.u64 t, %1; cvt.u32.u64 %0, t; }"
      : "=r"(a) : "l"(p));
  return a;
}

__device__ __forceinline__ void ldm4(uint32_t* d, uint32_t addr) {
  asm volatile("ldmatrix.sync.aligned.m8n8.x4.shared.b16 {%0,%1,%2,%3}, [%4];"
               : "=r"(d[0]), "=r"(d[1]), "=r"(d[2]), "=r"(d[3]) : "r"(addr));
}

__device__ __forceinline__ void mma16816(float* c, const uint32_t* a,
                                         const uint32_t* b) {
  asm volatile(
      "mma.sync.aligned.m16n8k16.row.col.f32.bf16.bf16.f32 "
      "{%0,%1,%2,%3}, {%4,%5,%6,%7}, {%8,%9}, {%0,%1,%2,%3};"
      : "+f"(c[0]), "+f"(c[1]), "+f"(c[2]), "+f"(c[3])
      : "r"(a[0]), "r"(a[1]), "r"(a[2]), "r"(a[3]), "r"(b[0]), "r"(b[1]));
}

__device__ __forceinline__ void sts_v2(uint32_t addr, uint32_t a, uint32_t b) {
  asm volatile("st.shared.v2.b32 [%0], {%1,%2};" :: "r"(addr), "r"(a), "r"(b));
}
__device__ __forceinline__ void sts32(uint32_t addr, uint32_t a) {
  asm volatile("st.shared.b32 [%0], %1;" :: "r"(addr), "r"(a));
}

// bf16 hi/lo split: hi = bf16(x); lo = bf16(x - hi).
__device__ __forceinline__ uint16_t bfc(float x, int lo) {
  __nv_bfloat16 h = __float2bfloat16(x);
  if (lo) h = __float2bfloat16(x - __bfloat162float(h));
  return __bfloat16_as_ushort(h);
}
__device__ __forceinline__ uint32_t pack2(float x, float y, int lo) {
  return (uint32_t)bfc(x, lo) | ((uint32_t)bfc(y, lo) << 16);
}

// --------------------------- staged tile loaders -----------------------------
// SMEM tile: 128 rows x 32 bf16, row stride 80 bytes (conflict-free ldmatrix).

constexpr int ROWB = 80;
constexpr int TILEB = 128 * ROWB;  // 10240

// Rows-major operand (rows = M or N, cols = K): fetch global -> regs.
__device__ __forceinline__ void fetch_km(const float* S, int ld, int rmax,
                                         int Kmax, int r0, int k0, int tid,
                                         float4* v) {
#pragma unroll
  for (int i = 0; i < 4; i++) {
    int idx = tid + 256 * i;        // 1024 float4 slots
    int row = idx >> 3;             // 8 float4 per row
    int kq = idx & 7;
    int gr = r0 + row, gk = k0 + kq * 4;
    v[i] = make_float4(0.f, 0.f, 0.f, 0.f);
    if (gr < rmax) {
      const float* sp = S + (size_t)gr * ld;
      if (gk + 3 < Kmax) {
        v[i] = *reinterpret_cast<const float4*>(sp + gk);
      } else {
        if (gk < Kmax)     v[i].x = sp[gk];
        if (gk + 1 < Kmax) v[i].y = sp[gk + 1];
        if (gk + 2 < Kmax) v[i].z = sp[gk + 2];
        if (gk + 3 < Kmax) v[i].w = sp[gk + 3];
      }
    }
  }
}

__device__ __forceinline__ void commit_km(uint32_t hiB, uint32_t loB,
                                          bool doLo, int tid, const float4* v) {
#pragma unroll
  for (int i = 0; i < 4; i++) {
    int idx = tid + 256 * i;
    int row = idx >> 3;
    int kq = idx & 7;
    uint32_t off = (uint32_t)(row * ROWB + kq * 8);
    sts_v2(hiB + off, pack2(v[i].x, v[i].y, 0), pack2(v[i].z, v[i].w, 0));
    if (doLo) sts_v2(loB + off, pack2(v[i].x, v[i].y, 1), pack2(v[i].z, v[i].w, 1));
  }
}

// B stored (K,N) row-major (transpose on commit): fetch global -> regs.
__device__ __forceinline__ void fetch_tr(const float* S, int ld, int nmax,
                                         int Kmax, int n0, int k0, int tid,
                                         float4* t0, float4* t1) {
#pragma unroll
  for (int i = 0; i < 2; i++) {
    int u = tid + 256 * i;          // 512 pair-units
    int n4 = u & 31;                // group of 4 N values
    int k = (u >> 5) * 2;           // even k
    int gk = k0 + k, gn = n0 + n4 * 4;
    t0[i] = make_float4(0.f, 0.f, 0.f, 0.f);
    t1[i] = make_float4(0.f, 0.f, 0.f, 0.f);
    if (gn + 3 < nmax) {
      if (gk < Kmax)
        t0[i] = *reinterpret_cast<const float4*>(S + (size_t)gk * ld + gn);
      if (gk + 1 < Kmax)
        t1[i] = *reinterpret_cast<const float4*>(S + (size_t)(gk + 1) * ld + gn);
    } else {
      float* p0 = reinterpret_cast<float*>(&t0[i]);
      float* p1 = reinterpret_cast<float*>(&t1[i]);
#pragma unroll
      for (int jj = 0; jj < 4; jj++) {
        if (gn + jj < nmax) {
          if (gk < Kmax)     p0[jj] = S[(size_t)gk * ld + gn + jj];
          if (gk + 1 < Kmax) p1[jj] = S[(size_t)(gk + 1) * ld + gn + jj];
        }
      }
    }
  }
}

__device__ __forceinline__ void commit_tr(uint32_t hiB, uint32_t loB,
                                          bool doLo, int tid, const float4* t0,
                                          const float4* t1) {
#pragma unroll
  for (int i = 0; i < 2; i++) {
    int u = tid + 256 * i;
    int n4 = u & 31;
    int k = (u >> 5) * 2;
    const float* p0 = reinterpret_cast<const float*>(&t0[i]);
    const float* p1 = reinterpret_cast<const float*>(&t1[i]);
#pragma unroll
    for (int jj = 0; jj < 4; jj++) {
      uint32_t off = (uint32_t)((n4 * 4 + jj) * ROWB + k * 2);
      sts32(hiB + off, pack2(p0[jj], p1[jj], 0));
      if (doLo) sts32(loB + off, pack2(p0[jj], p1[jj], 1));
    }
  }
}

// ----------------------------- HMMA GEMM kernel -----------------------------
// C[M,N] = A[M,K] * op(B); tile 128(M) x 128(N) x 32(K-chunk); 256 threads.
// SPLIT: per chunk run 3 sub-passes hiA*hiB + loA*hiB + hiA*loB.
// Pipeline: fetch(k+1) -> regs issued before compute(k); commit after.

template <typename P, bool SPLIT>
__global__ __launch_bounds__(256) void gemm_mm(P p) {
  __shared__ __align__(16) char sm[4 * TILEB];  // Ahi, Alo, Bhi, Blo
  uint32_t base = smem_u32(sm);
  const uint32_t Ahi = base, Alo = base + TILEB;
  const uint32_t Bhi = base + 2 * TILEB, Blo = base + 3 * TILEB;

  const int tid = threadIdx.x;
  const int wid = tid >> 5, lane = tid & 31;
  const int wm = wid >> 1, wn = wid & 1;   // warp tile: 32(M) x 64(N)
  const int lj = lane >> 3, lr = lane & 7;

  const int z = blockIdx.z;
  const float* A = p.Aptr(z);
  const float* Bm = p.Bptr(z);
  const int M = p.M, N = p.N, K = p.K, lda = p.lda, ldb = p.ldb;
  const int m0 = blockIdx.y * 128, n0 = blockIdx.x * 128;

  float acc[2][8][4];
#pragma unroll
  for (int a = 0; a < 2; a++)
#pragma unroll
    for (int b = 0; b < 8; b++)
#pragma unroll
      for (int c = 0; c < 4; c++) acc[a][b][c] = 0.f;

  const uint32_t aRow = (uint32_t)(wm * 32 + (lj & 1) * 8 + lr);
  const uint32_t aCol = (uint32_t)((lj >> 1) * 16);
  const uint32_t bRow = (uint32_t)(wn * 64 + (lj >> 1) * 8 + lr);
  const uint32_t bCol = (uint32_t)((lj & 1) * 16);

  // staged registers
  float4 av[4];
  float4 bv[4];          // used when P::BT (km path)
  float4 bt0[2], bt1[2]; // used when !P::BT (tr path)

  const int nch = (K + 31) >> 5;
  // prologue: fetch chunk 0
  fetch_km(A, lda, M, K, m0, 0, tid, av);
  if (P::BT) fetch_km(Bm, ldb, N, K, n0, 0, tid, bv);
  else       fetch_tr(Bm, ldb, N, K, n0, 0, tid, bt0, bt1);

  for (int ch = 0; ch < nch; ch++) {
    // commit staged chunk into SMEM
    commit_km(Ahi, Alo, SPLIT, tid, av);
    if (P::BT) commit_km(Bhi, Blo, SPLIT, tid, bv);
    else       commit_tr(Bhi, Blo, SPLIT, tid, bt0, bt1);
    __syncthreads();

    // issue next chunk's global loads (overlap with compute below)
    if (ch + 1 < nch) {
      int k1 = (ch + 1) << 5;
      fetch_km(A, lda, M, K, m0, k1, tid, av);
      if (P::BT) fetch_km(Bm, ldb, N, K, n0, k1, tid, bv);
      else       fetch_tr(Bm, ldb, N, K, n0, k1, tid, bt0, bt1);
    }

    const int npass = SPLIT ? 3 : 1;
#pragma unroll 1
    for (int ps = 0; ps < npass; ps++) {
      uint32_t aT = (ps == 1) ? Alo : Ahi;
      uint32_t bT = (ps == 2) ? Blo : Bhi;
#pragma unroll
      for (int ks = 0; ks < 2; ks++) {
        uint32_t afr[2][4];
#pragma unroll
        for (int mi = 0; mi < 2; mi++)
          ldm4(afr[mi], aT + (aRow + mi * 16) * ROWB + ks * 32 + aCol);
        uint32_t bfr[8][2];
#pragma unroll
        for (int nb = 0; nb < 4; nb++) {
          uint32_t t[4];
          ldm4(t, bT + (bRow + nb * 16) * ROWB + ks * 32 + bCol);
          bfr[2 * nb][0] = t[0];
          bfr[2 * nb][1] = t[1];
          bfr[2 * nb + 1][0] = t[2];
          bfr[2 * nb + 1][1] = t[3];
        }
#pragma unroll
        for (int mi = 0; mi < 2; mi++)
#pragma unroll
          for (int ni = 0; ni < 8; ni++)
            mma16816(acc[mi][ni], afr[mi], bfr[ni]);
      }
    }
    __syncthreads();  // SMEM consumed; safe to overwrite next iteration
  }

  // Epilogue.
  const int rr = lane >> 2, cc = (lane & 3) * 2;
#pragma unroll
  for (int mi = 0; mi < 2; mi++) {
#pragma unroll
    for (int ni = 0; ni < 8; ni++) {
      int rb = m0 + wm * 32 + mi * 16 + rr;
      int cb = n0 + wn * 64 + ni * 8 + cc;
      if (rb < M) {
        if (cb < N)     p.store(z, rb, cb,     acc[mi][ni][0]);
        if (cb + 1 < N) p.store(z, rb, cb + 1, acc[mi][ni][1]);
      }
      if (rb + 8 < M) {
        if (cb < N)     p.store(z, rb + 8, cb,     acc[mi][ni][2]);
        if (cb + 1 < N) p.store(z, rb + 8, cb + 1, acc[mi][ni][3]);
      }
    }
  }
}

// ----------------------------- GEMM problem defs ----------------------------

struct WeffP {
  static constexpr bool BT = false;
  int M, N, K, lda, ldb;
  const float* wpT;
  const float* Wq; const float* Wk; const float* Wv;
  float* Weff;
  __device__ const float* Aptr(int z) const {
    int ti = z >> 5, t = z & 3;
    return wpT + ((size_t)(ti * 4 + t) << 18);
  }
  __device__ const float* Bptr(int z) const {
    int ti = z >> 5, n = (z & 31) >> 2;
    const float* W = (ti == 0) ? Wq : ((ti == 1) ? Wk : Wv);
    return W + (size_t)n * 512 * 512;
  }
  __device__ void store(int z, int r, int c, float v) const {
    int ti = z >> 5, n = (z & 31) >> 2, t = z & 3;
    Weff[(size_t)ti * 4096 * 2048 + (size_t)(n * 512 + r) * 2048 + t * 512 + c] = v;
  }
};

struct PoolP {
  static constexpr bool BT = true;
  int M, N, K, lda, ldb;
  const float* Xg;
  const float* Weff;
  const float* bias;  // may be null
  float* out;
  int nh;
  __device__ const float* Aptr(int) const { return Xg; }
  __device__ const float* Bptr(int) const { return Weff; }
  __device__ void store(int, int r, int c, float v) const {
    int b = r / NB_, o = r % NB_;
    if (bias) v += bias[c];
    out[((size_t)(b * nh + (c >> 9)) * LP_ + 1 + o) * 512 + (c & 511)] = v;
  }
};

struct LogitsP {
  static constexpr bool BT = true;
  int M, N, K, lda, ldb;
  const float* PQ;
  const float* K2;
  float* lg;
  __device__ const float* Aptr(int z) const { return PQ + (size_t)z * LP_ * 512; }
  __device__ const float* Bptr(int z) const { return K2 + (size_t)z * LP_ * 512; }
  __device__ void store(int z, int r, int c, float v) const {
    lg[(size_t)z * LP_ * LGLD_ + (size_t)r * LGLD_ + c] = v;
  }
};

struct AVP {
  static constexpr bool BT = false;
  int M, N, K, lda, ldb;
  const float* attn;
  const float* PV;
  const float* PQ;
  float* stacked;
  __device__ const float* Aptr(int z) const { return attn + (size_t)z * LP_ * LGLD_; }
  __device__ const float* Bptr(int z) const { return PV + (size_t)z * LP_ * 512; }
  __device__ void store(int z, int r, int c, float v) const {
    float pq = PQ[(size_t)z * LP_ * 512 + (size_t)r * 512 + c];
    v += (r > 0 ? 2.f : 1.f) * pq;
    int b = z >> 3, n = z & 7;
    stacked[((size_t)b * LP_ + r) * 4096 + n * 512 + c] = v;
  }
};

struct FinalP {
  static constexpr bool BT = true;
  int M, N, K, lda, ldb;
  const float* stacked;
  const float* Wd;
  const float* bd;
  const float* PX;
  float* y;
  __device__ const float* Aptr(int) const { return stacked; }
  __device__ const float* Bptr(int) const { return Wd; }
  __device__ void store(int, int r, int c, float v) const {
    y[(size_t)r * 512 + c] = v + bd[c] + PX[(size_t)r * 512 + c];
  }
};

// ------------------------------ helper kernels ------------------------------

__global__ void k_transpose_wp(const float* wpq, const float* wpk,
                               const float* wpv, float* wpT) {
  size_t idx = (size_t)blockIdx.x * blockDim.x + threadIdx.x;
  if (idx >= SZ_WPT) return;
  int ti = (int)(idx / (512 * 512 * 4));
  int r = (int)(idx % (512 * 512 * 4));
  int c = r / 2048;
  int d = (r % 2048) >> 2;
  int t = r & 3;
  const float* wp = (ti == 0) ? wpq : ((ti == 1) ? wpk : wpv);
  wpT[((size_t)(ti * 4 + t) * 512 + c) * 512 + d] = wp[r];
}

__global__ void k_wxe(const float* wpx, float* WXe) {
  size_t idx = (size_t)blockIdx.x * blockDim.x + threadIdx.x;
  if (idx >= SZ_WXE) return;
  int c = (int)(idx / 2048);
  int t = (int)((idx % 2048) / 512);
  int m = (int)(idx & 511);
  WXe[idx] = wpx[(size_t)c * 2048 + m * 4 + t];
}

__global__ void k_bpool(const float* wpq, const float* wpk, const float* wpv,
                        const float* bq, const float* bk, const float* bv,
                        float* bpool) {
  int j = blockIdx.x * blockDim.x + threadIdx.x;
  if (j >= 3 * 4096) return;
  int ti = j / 4096, h = j % 4096, n = h >> 9, c = h & 511;
  const float* wp = (ti == 0) ? wpq : ((ti == 1) ? wpk : wpv);
  const float* b = (ti == 0) ? bq : ((ti == 1) ? bk : bv);
  float s = 0.f;
  for (int d = 0; d < 512; d++) {
    float bb = b[n * 512 + d];
    const float* w = wp + (size_t)c * 2048 + d * 4;
    s += (w[0] + w[1] + w[2] + w[3]) * bb;
  }
  bpool[j] = s;
}

__global__ void k_gather(const float* x, float* Xg) {
  size_t idx = (size_t)blockIdx.x * blockDim.x + threadIdx.x;
  if (idx >= SZ_XG) return;
  int r = (int)(idx / 2048);
  int col = (int)(idx & 2047);
  int t = col >> 9, m = col & 511;
  int b = r / NB_, o = r % NB_;
  int t2 = o / 196, hh = (o / 14) % 14, ww = o % 14;
  int kh = t >> 1, kw = t & 1;
  int row = 1 + (t2 * 28 + 2 * hh + kh) * 28 + 2 * ww + kw;
  Xg[idx] = x[((size_t)b * L_ + row) * 512 + m];
}

__global__ void k_cls(const float* x, const float* Wq, const float* bq,
                      const float* Wk, const float* bk, const float* Wv,
                      const float* bv, float* PQ, float* PK, float* PV,
                      float* PX) {
  int idx = blockIdx.x * blockDim.x + threadIdx.x;
  if (idx < 2 * 12288) {
    int b = idx / 12288, j = idx % 12288, ti = j / 4096, jj = j & 4095;
    const float* W = (ti == 0) ? Wq : ((ti == 1) ? Wk : Wv);
    const float* bias = (ti == 0) ? bq : ((ti == 1) ? bk : bv);
    const float* xr = x + (size_t)b * L_ * 512;
    const float* wr = W + (size_t)jj * 512;
    float s = bias[jj];
    for (int m = 0; m < 512; m++) s += xr[m] * wr[m];
    int n = jj >> 9, c = jj & 511;
    float* out = (ti == 0) ? PQ : ((ti == 1) ? PK : PV);
    out[(size_t)(b * 8 + n) * LP_ * 512 + c] = s;
  } else if (idx < 2 * 12288 + 2 * 512) {
    int k = idx - 2 * 12288;
    int b = k >> 9, c = k & 511;
    PX[(size_t)b * LP_ * 512 + c] = x[(size_t)b * L_ * 512 + c];
  }
}

__device__ __forceinline__ float sincos_val(int pos, int c, int dim) {
  int half = dim / 2;
  bool is_cos = c >= half;
  int i = is_cos ? c - half : c;
  float omega = powf(10000.f, -((float)i) / (float)half);
  float ang = (float)pos * omega;
  return is_cos ? cosf(ang) : sinf(ang);
}

__global__ void k_emb(float* emb) {
  size_t idx = (size_t)blockIdx.x * blockDim.x + threadIdx.x;
  if (idx >= SZ_EMB) return;
  int k = (int)(idx >> 9);
  int c = (int)(idx & 511);
  int t2 = k / 196, h2 = (k / 14) % 14, w2 = k % 14;
  float v;
  if (c < 170) v = sincos_val(t2, c, 170);
  else if (c < 340) v = sincos_val(h2, c - 170, 170);
  else v = sincos_val(w2, c - 340, 172);
  emb[idx] = v;
}

__global__ void k_k2(const float* PK, const float* emb, float* K2) {
  size_t idx = (size_t)blockIdx.x * blockDim.x + threadIdx.x;
  if (idx >= SZ_P) return;
  size_t rem = idx % ((size_t)LP_ * 512);
  int k = (int)(rem >> 9);
  int c = (int)(rem & 511);
  float v = SCALE_ * PK[idx];
  if (k > 0) v += emb[(size_t)(k - 1) * 512 + c];
  K2[idx] = v;
}

__global__ void k_row0(const float* PQ, const float* PK, float* lg) {
  int z = blockIdx.y;
  int kq = blockIdx.x * 8 + (threadIdx.x >> 5);
  int lane = threadIdx.x & 31;
  if (kq >= LP_) return;
  const float* q = PQ + (size_t)z * LP_ * 512;
  const float* kr = PK + (size_t)z * LP_ * 512 + (size_t)kq * 512;
  float s = 0.f;
  for (int i = lane; i < 512; i += 32) s += q[i] * kr[i];
#pragma unroll
  for (int o = 16; o; o >>= 1) s += __shfl_xor_sync(0xFFFFFFFFu, s, o);
  if (lane == 0) lg[(size_t)z * LP_ * LGLD_ + kq] = s * SCALE_;
}

__global__ void k_softmax(float* lg) {
  int z = blockIdx.y, q = blockIdx.x;
  float* row = lg + ((size_t)z * LP_ + q) * LGLD_;
  int tid = threadIdx.x;
  __shared__ float red[256];
  float mx = -1e30f;
  for (int i = tid; i < LP_; i += 256) mx = fmaxf(mx, row[i]);
  red[tid] = mx;
  __syncthreads();
  for (int s = 128; s > 0; s >>= 1) {
    if (tid < s) red[tid] = fmaxf(red[tid], red[tid + s]);
    __syncthreads();
  }
  mx = red[0];
  __syncthreads();
  float sum = 0.f;
  for (int i = tid; i < LP_; i += 256) {
    float e = expf(row[i] - mx);
    row[i] = e;
    sum += e;
  }
  red[tid] = sum;
  __syncthreads();
  for (int s = 128; s > 0; s >>= 1) {
    if (tid < s) red[tid] += red[tid + s];
    __syncthreads();
  }
  float inv = 1.f / red[0];
  for (int i = tid; i < LP_; i += 256) row[i] *= inv;
}

__global__ void k_ln(float* y, const float* gamma, const float* beta) {
  int row = blockIdx.x;
  float* yr = y + (size_t)row * 512;
  int tid = threadIdx.x;
  float v0 = yr[tid], v1 = yr[tid + 256];
  __shared__ float red[256];
  red[tid] = v0 + v1;
  __syncthreads();
  for (int s = 128; s > 0; s >>= 1) {
    if (tid < s) red[tid] += red[tid + s];
    __syncthreads();
  }
  float mu = red[0] * (1.f / 512.f);
  __syncthreads();
  float d0 = v0 - mu, d1 = v1 - mu;
  red[tid] = d0 * d0 + d1 * d1;
  __syncthreads();
  for (int s = 128; s > 0; s >>= 1) {
    if (tid < s) red[tid] += red[tid + s];
    __syncthreads();
  }
  float inv = rsqrtf(red[0] * (1.f / 512.f) + 1e-5f);
  yr[tid] = d0 * inv * gamma[tid] + beta[tid];
  yr[tid + 256] = d1 * inv * gamma[tid + 256] + beta[tid + 256];
}

// --------------------------------- launcher ---------------------------------

extern "C" void kernel_launch(void* const* d_in, const int* in_sizes, int n_in,
                              void* d_out, int out_size) {
  (void)in_sizes; (void)n_in; (void)out_size;
  const float* x   = (const float*)d_in[0];
  const float* Wq  = (const float*)d_in[1];
  const float* bq  = (const float*)d_in[2];
  const float* Wk  = (const float*)d_in[3];
  const float* bk  = (const float*)d_in[4];
  const float* Wv  = (const float*)d_in[5];
  const float* bv  = (const float*)d_in[6];
  const float* wpq = (const float*)d_in[7];
  const float* wpk = (const float*)d_in[8];
  const float* wpv = (const float*)d_in[9];
  const float* wpx = (const float*)d_in[10];
  const float* Wd  = (const float*)d_in[11];
  const float* bd  = (const float*)d_in[12];
  const float* gamma = (const float*)d_in[13];
  const float* beta  = (const float*)d_in[14];
  float* y = (float*)d_out;

  float* S = nullptr;
  cudaGetSymbolAddress((void**)&S, g_scratch);

  float* wpT   = S + OFF_WPT;
  float* Weff  = S + OFF_WEFF;
  float* WXe   = S + OFF_WXE;
  float* bpool = S + OFF_BP;
  float* Xg    = S + OFF_XG;
  float* PQ    = S + OFF_PQ;
  float* PK    = S + OFF_PK;
  float* PV    = S + OFF_PV;
  float* K2    = S + OFF_K2;
  float* PX    = S + OFF_PX;
  float* emb   = S + OFF_EMB;
  float* lg    = S + OFF_LG;
  float* st    = S + OFF_ST;

  k_transpose_wp<<<(int)((SZ_WPT + 255) / 256), 256>>>(wpq, wpk, wpv, wpT);
  k_wxe<<<(int)((SZ_WXE + 255) / 256), 256>>>(wpx, WXe);
  k_bpool<<<(3 * 4096 + 255) / 256, 256>>>(wpq, wpk, wpv, bq, bk, bv, bpool);

  {
    WeffP p;
    p.M = 512; p.N = 512; p.K = 512; p.lda = 512; p.ldb = 512;
    p.wpT = wpT; p.Wq = Wq; p.Wk = Wk; p.Wv = Wv; p.Weff = Weff;
    gemm_mm<WeffP, true><<<dim3(4, 4, 96), 256>>>(p);
  }

  k_gather<<<(int)((SZ_XG + 255) / 256), 256>>>(x, Xg);

  {
    PoolP p;
    p.M = B_ * NB_; p.K = 2048; p.lda = 2048; p.ldb = 2048;
    p.Xg = Xg;
    p.N = 4096; p.nh = 8;
    p.Weff = Weff;                           p.bias = bpool;        p.out = PQ;
    gemm_mm<PoolP, true><<<dim3(32, 25, 1), 256>>>(p);
    p.Weff = Weff + (size_t)4096 * 2048;     p.bias = bpool + 4096; p.out = PK;
    gemm_mm<PoolP, false><<<dim3(32, 25, 1), 256>>>(p);
    p.Weff = Weff + (size_t)2 * 4096 * 2048; p.bias = bpool + 8192; p.out = PV;
    gemm_mm<PoolP, true><<<dim3(32, 25, 1), 256>>>(p);
    p.N = 512; p.nh = 1;
    p.Weff = WXe; p.bias = nullptr; p.out = PX;
    gemm_mm<PoolP, true><<<dim3(4, 25, 1), 256>>>(p);
  }

  k_cls<<<(2 * 12288 + 2 * 512 + 255) / 256, 256>>>(x, Wq, bq, Wk, bk, Wv, bv,
                                                    PQ, PK, PV, PX);
  k_emb<<<(int)((SZ_EMB + 255) / 256), 256>>>(emb);
  k_k2<<<(int)((SZ_P + 255) / 256), 256>>>(PK, emb, K2);

  {
    LogitsP p;
    p.M = LP_; p.N = LP_; p.K = 512; p.lda = 512; p.ldb = 512;
    p.PQ = PQ; p.K2 = K2; p.lg = lg;
    gemm_mm<LogitsP, true><<<dim3(13, 13, 16), 256>>>(p);
  }

  k_row0<<<dim3((LP_ + 7) / 8, 16), 256>>>(PQ, PK, lg);
  k_softmax<<<dim3(LP_, 16), 256>>>(lg);

  {
    AVP p;
    p.M = LP_; p.N = 512; p.K = LP_; p.lda = LGLD_; p.ldb = 512;
    p.attn = lg; p.PV = PV; p.PQ = PQ; p.stacked = st;
    gemm_mm<AVP, true><<<dim3(4, 13, 16), 256>>>(p);
  }

  {
    FinalP p;
    p.M = B_ * LP_; p.N = 512; p.K = 4096; p.lda = 4096; p.ldb = 4096;
    p.stacked = st; p.Wd = Wd; p.bd = bd; p.PX = PX; p.y = y;
    gemm_mm<FinalP, true><<<dim3(4, 25, 1), 256>>>(p);
  }

  k_ln<<<B_ * LP_, 256>>>(y, gamma, beta);
}